// round 1
// baseline (speedup 1.0000x reference)
#include <cuda_runtime.h>

// ----------------------------------------------------------------------------
// Despawn2D: 6-level 2D db4 circular DWT + sigmoid threshold + inverse DWT.
// N = 4096 (power of two, no padding). Filter length 8.
// d_out layout: [ recon (4096*4096) | flat coeffs (4096*4096) ]
// flat: per level lev, block of shape (s2, 3*s2) row-major = hh|hl|lh rows,
//       then final thresholded approx (64*64).
// ----------------------------------------------------------------------------

#define NSIDE 4096

// Scratch (static device allocations — allowed; no cudaMalloc anywhere).
__device__ float g_bufA[2048u * 2048u];   // approx ping (16 MB)
__device__ float g_bufB[2048u * 2048u];   // approx pong (16 MB)
__device__ float g_D  [4096u * 2048u];    // row detail / h_mat (32 MB)
__device__ float g_Ar [4096u * 2048u];    // row approx / l_mat (32 MB)

__device__ __forceinline__ float thrf(float t, float alpha, float bp, float bm)
{
    // t * ( sigmoid(alpha*(t-bp)) + sigmoid(-alpha*(t+bm)) )
    float s1 = 1.0f / (1.0f + expf(-alpha * (t - bp)));
    float s2 = 1.0f / (1.0f + expf( alpha * (t + bm)));
    return t * (s1 + s2);
}

// ----------------------------------------------------------------------------
// Forward along rows: D[r,j] = sum_k w[k] X[r,(2j-k)&mask],  A same with h.
// Block: BW threads over j of one row. smem holds the 2*BW+7 input window.
// ----------------------------------------------------------------------------
__global__ void fwd_rows(const float* __restrict__ X, int ldx, int L,
                         float* __restrict__ D, float* __restrict__ A, int ldo,
                         const float* __restrict__ hF)
{
    extern __shared__ float sx[];
    __shared__ float h[8], w[8];
    const int tx = threadIdx.x;
    const int BW = blockDim.x;
    if (tx < 8) h[tx] = hF[tx];
    __syncthreads();
    if (tx < 8) w[tx] = h[7 - tx] * ((tx & 1) ? -1.0f : 1.0f);

    const int r    = blockIdx.y;
    const int j0   = blockIdx.x * BW;
    const int mask = L - 1;
    const int base = 2 * j0 - 7;
    const float* xr = X + (size_t)r * ldx;
    const int NS = 2 * BW + 7;
    for (int t = tx; t < NS; t += BW)
        sx[t] = xr[(base + t) & mask];
    __syncthreads();

    const int j = j0 + tx;
    if (j < (L >> 1)) {
        float dv = 0.f, av = 0.f;
        const int b = 2 * tx;
#pragma unroll
        for (int m = 0; m < 8; m++) {
            float xv = sx[b + m];          // = X[r, (2j - (7-m)) & mask]
            dv += w[7 - m] * xv;
            av += h[7 - m] * xv;
        }
        D[(size_t)r * ldo + j] = dv;
        A[(size_t)r * ldo + j] = av;
    }
}

// ----------------------------------------------------------------------------
// Forward along columns: OD[i,j] = sum_k w[k] M[(2i-k)&(R-1), j], OA with h.
// Detail output always thresholded; approx thresholded iff thrApprox.
// Block (32,8): 32 cols x 8 output rows; smem tile 23 x 32 input rows.
// ----------------------------------------------------------------------------
__global__ void fwd_cols(const float* __restrict__ M, int R, int C, int ldm,
                         float* __restrict__ OD, long ldd,
                         float* __restrict__ OA, long lda,
                         const float* __restrict__ hF, int thrApprox,
                         const float* __restrict__ pA,
                         const float* __restrict__ pBp,
                         const float* __restrict__ pBm)
{
    __shared__ float sm[23][33];
    __shared__ float h[8], w[8];
    const int tx = threadIdx.x, ty = threadIdx.y;
    const int tid = ty * 32 + tx;
    if (tid < 8) h[tid] = hF[tid];
    __syncthreads();
    if (tid < 8) w[tid] = h[7 - tid] * ((tid & 1) ? -1.0f : 1.0f);

    const int j     = blockIdx.x * 32 + tx;
    const int i0    = blockIdx.y * 8;
    const int maskR = R - 1;
    const int rbase = 2 * i0 - 7;
    const bool jok  = (j < C);
    for (int t = ty; t < 23; t += 8) {
        int rr = (rbase + t) & maskR;
        sm[t][tx] = jok ? M[(size_t)rr * ldm + j] : 0.0f;
    }
    __syncthreads();

    const int i = i0 + ty;
    if (jok && i < (R >> 1)) {
        float dv = 0.f, av = 0.f;
        const int b = 2 * ty;
#pragma unroll
        for (int m = 0; m < 8; m++) {
            float xv = sm[b + m][tx];
            dv += w[7 - m] * xv;
            av += h[7 - m] * xv;
        }
        const float alpha = *pA, bp = *pBp, bm = *pBm;
        dv = thrf(dv, alpha, bp, bm);
        if (thrApprox) av = thrf(av, alpha, bp, bm);
        OD[(long)i * ldd + j] = dv;
        OA[(long)i * lda + j] = av;
    }
}

// ----------------------------------------------------------------------------
// Backward along columns (upsample + correlate):
// H[i,j] = sum_{u=0..3} w[2u+p] D[(m0+u)&(R2-1), j] + h[2u+p] A[...],
// p = i&1, m0 = (i+p)>>1.  H has 2*R2 rows.
// ----------------------------------------------------------------------------
__global__ void bwd_cols(const float* __restrict__ D, long ldD,
                         const float* __restrict__ A, long ldA,
                         int R2, int C,
                         float* __restrict__ H, long ldH,
                         const float* __restrict__ hF)
{
    __shared__ float h[8], w[8];
    const int tx = threadIdx.x, ty = threadIdx.y;
    const int tid = ty * 32 + tx;
    if (tid < 8) h[tid] = hF[tid];
    __syncthreads();
    if (tid < 8) w[tid] = h[7 - tid] * ((tid & 1) ? -1.0f : 1.0f);
    __syncthreads();

    const int j = blockIdx.x * 32 + tx;
    const int i = blockIdx.y * blockDim.y + ty;
    if (j >= C || i >= 2 * R2) return;
    const int p    = i & 1;
    const int m0   = (i + p) >> 1;
    const int mask = R2 - 1;
    float acc = 0.f;
#pragma unroll
    for (int u = 0; u < 4; u++) {
        int m = (m0 + u) & mask;
        acc += w[2 * u + p] * D[(long)m * ldD + j]
             + h[2 * u + p] * A[(long)m * ldA + j];
    }
    H[(long)i * ldH + j] = acc;
}

// ----------------------------------------------------------------------------
// Backward along rows:
// X[r,i] = sum_u w[2u+p] Hm[r,(m0+u)&(C2-1)] + h[2u+p] Lm[r,...].
// Block: BW threads over i of one row; smem holds BW/2+4 elems of each input.
// ----------------------------------------------------------------------------
__global__ void bwd_rows(const float* __restrict__ Hm,
                         const float* __restrict__ Lm, long ldi, int C2,
                         float* __restrict__ X, long ldX,
                         const float* __restrict__ hF)
{
    extern __shared__ float smr[];
    __shared__ float h[8], w[8];
    const int tx = threadIdx.x;
    const int BW = blockDim.x;
    if (tx < 8) h[tx] = hF[tx];
    __syncthreads();
    if (tx < 8) w[tx] = h[7 - tx] * ((tx & 1) ? -1.0f : 1.0f);

    const int r    = blockIdx.y;
    const int i0   = blockIdx.x * BW;       // even (BW multiple of 2)
    const int NS   = BW / 2 + 4;
    const int base = i0 >> 1;
    const int mask = C2 - 1;
    float* sH = smr;
    float* sL = smr + NS;
    const float* hr = Hm + (long)r * ldi;
    const float* lr = Lm + (long)r * ldi;
    for (int t = tx; t < NS; t += BW) {
        int m = (base + t) & mask;
        sH[t] = hr[m];
        sL[t] = lr[m];
    }
    __syncthreads();

    const int i = i0 + tx;
    if (i < 2 * C2) {
        const int p  = tx & 1;               // i0 even -> parity of i == parity of tx
        const int m0 = (tx + p) >> 1;        // local offset into smem window
        float acc = 0.f;
#pragma unroll
        for (int u = 0; u < 4; u++)
            acc += w[2 * u + p] * sH[m0 + u] + h[2 * u + p] * sL[m0 + u];
        X[(long)r * ldX + i] = acc;
    }
}

// ----------------------------------------------------------------------------
// Host orchestration (graph-capturable: kernel launches only).
// ----------------------------------------------------------------------------
extern "C" void kernel_launch(void* const* d_in, const int* in_sizes, int n_in,
                              void* d_out, int out_size)
{
    const float* x    = (const float*)d_in[0];   // (4096, 4096)
    const float* scal = (const float*)d_in[1];   // (12, 8)
    const float* pA   = (const float*)d_in[2];   // alpha
    const float* pBp  = (const float*)d_in[3];   // b_plus
    const float* pBm  = (const float*)d_in[4];   // b_minus

    float* out  = (float*)d_out;                       // recon 4096x4096
    float* flat = out + (size_t)NSIDE * NSIDE;         // coeff region

    float *bufA, *bufB, *Dbuf, *Abuf;
    cudaGetSymbolAddress((void**)&bufA, g_bufA);
    cudaGetSymbolAddress((void**)&bufB, g_bufB);
    cudaGetSymbolAddress((void**)&Dbuf, g_D);
    cudaGetSymbolAddress((void**)&Abuf, g_Ar);

    // flat offsets per level + final approx
    size_t levoff[6];
    size_t off = 0;
    {
        long t2 = 2048;
        for (int l = 0; l < 6; l++) { levoff[l] = off; off += 3ull * t2 * t2; t2 >>= 1; }
    }
    const size_t approxoff = off;   // 16,773,120; +4096 = 16,777,216

    // ---------------- forward ----------------
    const float* cur = x;
    int s = NSIDE;
    for (int lev = 0; lev < 6; lev++) {
        const int s2 = s >> 1;
        const float* hH = scal + lev * 8;
        const float* hV = scal + (lev + 1) * 8;

        {   // rows: cur (s x s) -> Dbuf, Abuf (s x s2)
            dim3 blk(128, 1), grd((s2 + 127) / 128, s);
            fwd_rows<<<grd, blk, (2 * 128 + 7) * sizeof(float)>>>(
                cur, s, s, Dbuf, Abuf, s2, hH);
        }

        float* base = flat + levoff[lev];
        dim3 cblk(32, 8), cgrd((s2 + 31) / 32, s >> 4);
        // columns of D -> hh (thr), hl (thr), both into flat interleaved layout
        fwd_cols<<<cgrd, cblk>>>(Dbuf, s, s2, s2,
                                 base,            3L * s2,
                                 base + s2,       3L * s2,
                                 hV, /*thrApprox=*/1, pA, pBp, pBm);
        // columns of A -> lh (thr, flat), ll (approx; thresholded only at last level)
        float* ll;
        int thrA;
        if (lev == 5) { ll = flat + approxoff; thrA = 1; }
        else          { ll = (lev & 1) ? bufB : bufA; thrA = 0; }
        fwd_cols<<<cgrd, cblk>>>(Abuf, s, s2, s2,
                                 base + 2L * s2,  3L * s2,
                                 ll,              (long)s2,
                                 hV, thrA, pA, pBp, pBm);
        cur = ll;
        s = s2;
    }

    // ---------------- backward ----------------
    const float* aprev = flat + approxoff;  // thresholded final approx (64x64)
    long ldap = 64;
    for (int lev = 5; lev >= 0; lev--) {
        const int s2 = 2048 >> lev;  // coeff side
        const int so = s2 * 2;       // output side
        const float* hH = scal + lev * 8;
        const float* hV = scal + (lev + 1) * 8;
        const float* base = flat + levoff[lev];

        dim3 cblk(32, 8), cgrd((s2 + 31) / 32, so / 8);
        // columns: (hh, hl) -> h_mat (so x s2)
        bwd_cols<<<cgrd, cblk>>>(base,           3L * s2,
                                 base + s2,      3L * s2,
                                 s2, s2, Dbuf, (long)s2, hV);
        // columns: (lh, approx) -> l_mat (so x s2)
        bwd_cols<<<cgrd, cblk>>>(base + 2L * s2, 3L * s2,
                                 aprev,          ldap,
                                 s2, s2, Abuf, (long)s2, hV);

        float* xo; long ldx;
        if (lev == 0) { xo = out; ldx = NSIDE; }
        else          { xo = (lev & 1) ? bufB : bufA; ldx = so; }
        dim3 rblk(256, 1), rgrd((so + 255) / 256, so);
        bwd_rows<<<rgrd, rblk, 2 * (256 / 2 + 4) * sizeof(float)>>>(
            Dbuf, Abuf, (long)s2, s2, xo, ldx, hH);

        aprev = xo;
        ldap = ldx;
    }
}

// round 2
// speedup vs baseline: 1.6239x; 1.6239x over previous
#include <cuda_runtime.h>

// ----------------------------------------------------------------------------
// Despawn2D: 6-level 2D db4 circular DWT + sigmoid threshold + inverse DWT.
// Fused per-level kernels: one forward (rows+cols+threshold), one backward
// (col recon + row recon) per level. N = 4096.
// d_out layout: [ recon (4096*4096) | flat coeffs (4096*4096) ]
// flat per level: (s2, 3*s2) row-major hh|hl|lh, then approx (64*64) last.
// ----------------------------------------------------------------------------

#define NSIDE 4096

__device__ float g_bufA[2048u * 2048u];   // ll ping (16 MB)
__device__ float g_bufB[2048u * 2048u];   // ll pong (16 MB)

__device__ __forceinline__ float thrf(float t, float a, float bp, float bm)
{
    float s1 = 1.0f / (1.0f + __expf(-a * (t - bp)));
    float s2 = 1.0f / (1.0f + __expf( a * (t + bm)));
    return t * (s1 + s2);
}

// ----------------------------------------------------------------------------
// Fused forward: 32x32 output tile per block (256 threads).
// Input tile (with circular halo): 70x70. Row conv -> sd/sa (70x32),
// col conv -> hh,hl,lh (thresholded, to flat) + ll (to LL).
// ----------------------------------------------------------------------------
__global__ __launch_bounds__(256)
void fwd2d(const float* __restrict__ X, int s, long ldx,
           float* __restrict__ flatb,
           float* __restrict__ LL, long ldll, int thrLL,
           const float* __restrict__ hHp, const float* __restrict__ hVp,
           const float* __restrict__ pA, const float* __restrict__ pBp,
           const float* __restrict__ pBm)
{
    const int s2 = s >> 1;
    __shared__ float sx[70][72];
    __shared__ float sd[70][33];
    __shared__ float sa[70][33];
    __shared__ float hH[8], wH[8], hV[8], wV[8];
    const int tid = threadIdx.x;
    if (tid < 8) { hH[tid] = hHp[tid]; hV[tid] = hVp[tid]; }
    __syncthreads();
    if (tid < 8) {
        wH[tid] = hH[7 - tid] * ((tid & 1) ? -1.0f : 1.0f);
        wV[tid] = hV[7 - tid] * ((tid & 1) ? -1.0f : 1.0f);
    }

    const int i0 = blockIdx.y << 5, j0 = blockIdx.x << 5;
    const int mask = s - 1;
    const int rb = 2 * i0 - 7, cb = 2 * j0 - 7;

    // load input tile with circular wrap
    for (int t = tid; t < 70 * 70; t += 256) {
        int rr = t / 70, cc = t - rr * 70;
        sx[rr][cc] = X[(long)((rb + rr) & mask) * ldx + ((cb + cc) & mask)];
    }
    __syncthreads();   // also publishes wH/wV

    // row conv: D[r,j] = sum_m wH[7-m]*X[r, 2j-7+m] (local window sx[rr][2j+m])
    for (int t = tid; t < 70 * 32; t += 256) {
        int rr = t >> 5, j = t & 31;
        float dv = 0.f, av = 0.f;
#pragma unroll
        for (int m = 0; m < 8; m++) {
            float xv = sx[rr][2 * j + m];
            dv += wH[7 - m] * xv;
            av += hH[7 - m] * xv;
        }
        sd[rr][j] = dv;
        sa[rr][j] = av;
    }
    __syncthreads();

    const float alpha = *pA, bp = *pBp, bm = *pBm;
    const int tx = tid & 31, ty = tid >> 5;
    const int j = j0 + tx;
    const long ldflat = 3L * s2;
#pragma unroll
    for (int k = 0; k < 4; k++) {
        const int il = ty + (k << 3);
        const int i = i0 + il;
        float hhv = 0.f, hlv = 0.f, lhv = 0.f, llv = 0.f;
#pragma unroll
        for (int m = 0; m < 8; m++) {
            float dv = sd[2 * il + m][tx];
            float av = sa[2 * il + m][tx];
            hhv += wV[7 - m] * dv;
            hlv += hV[7 - m] * dv;
            lhv += wV[7 - m] * av;
            llv += hV[7 - m] * av;
        }
        const long ro = (long)i * ldflat;
        flatb[ro + j]             = thrf(hhv, alpha, bp, bm);
        flatb[ro + s2 + j]        = thrf(hlv, alpha, bp, bm);
        flatb[ro + 2 * s2 + j]    = thrf(lhv, alpha, bp, bm);
        LL[(long)i * ldll + j]    = thrLL ? thrf(llv, alpha, bp, bm) : llv;
    }
}

// ----------------------------------------------------------------------------
// Fused backward: 64x64 output tile per block (256 threads).
// Loads 36x36 tiles of hh/hl/lh/approx (circular halo), column reconstruction
// into sh/sl (64x36), then row reconstruction -> X tile.
//   col: h[i,j] = sum_u wV[2u+q] hh[(i+q)/2+u, j] + hV[2u+q] hl[...]  (q=i&1)
//   row: x[r,i] = sum_u wH[2u+p] h[r,(i+p)/2+u] + hH[2u+p] l[...]     (p=i&1)
// ----------------------------------------------------------------------------
__global__ __launch_bounds__(256)
void bwd2d(const float* __restrict__ base,   // hh | hl | lh, ld = 3*s2
           const float* __restrict__ ap, long lda,
           int s2,
           float* __restrict__ X, long ldx,
           const float* __restrict__ hHp, const float* __restrict__ hVp)
{
    __shared__ float shh[36][37], shl[36][37], slh[36][37], sll[36][37];
    __shared__ float sh[64][37], sl[64][37];
    __shared__ float hH[8], wH[8], hV[8], wV[8];
    const int tid = threadIdx.x;
    if (tid < 8) { hH[tid] = hHp[tid]; hV[tid] = hVp[tid]; }
    __syncthreads();
    if (tid < 8) {
        wH[tid] = hH[7 - tid] * ((tid & 1) ? -1.0f : 1.0f);
        wV[tid] = hV[7 - tid] * ((tid & 1) ? -1.0f : 1.0f);
    }

    const int i0 = blockIdx.y << 6, j0 = blockIdx.x << 6;
    const int mask = s2 - 1;
    const long ldc = 3L * s2;
    const int rb = i0 >> 1, cbb = j0 >> 1;

    for (int t = tid; t < 36 * 36; t += 256) {
        int rr = t / 36, cc = t - rr * 36;
        int gr = (rb + rr) & mask, gc = (cbb + cc) & mask;
        long o = (long)gr * ldc + gc;
        shh[rr][cc] = base[o];
        shl[rr][cc] = base[o + s2];
        slh[rr][cc] = base[o + 2 * s2];
        sll[rr][cc] = ap[(long)gr * lda + gc];
    }
    __syncthreads();   // also publishes wH/wV

    // column reconstruction: 64 local rows x 36 local cols
    for (int t = tid; t < 64 * 36; t += 256) {
        int r = t / 36, cc = t - r * 36;
        int q = r & 1;                 // i0 is even
        int m0 = (r + q) >> 1;         // local coeff-row offset, 0..32
        float hv = 0.f, lv = 0.f;
#pragma unroll
        for (int u = 0; u < 4; u++) {
            float f1 = wV[2 * u + q], f2 = hV[2 * u + q];
            hv += f1 * shh[m0 + u][cc] + f2 * shl[m0 + u][cc];
            lv += f1 * slh[m0 + u][cc] + f2 * sll[m0 + u][cc];
        }
        sh[r][cc] = hv;
        sl[r][cc] = lv;
    }
    __syncthreads();

    // row reconstruction
    const int tx = tid & 63, ty = tid >> 6;
    const int p = tx & 1;              // j0 is even
    const int m0 = (tx + p) >> 1;      // 0..32
#pragma unroll
    for (int k = 0; k < 16; k++) {
        const int r = ty + (k << 2);
        float acc = 0.f;
#pragma unroll
        for (int u = 0; u < 4; u++)
            acc += wH[2 * u + p] * sh[r][m0 + u]
                 + hH[2 * u + p] * sl[r][m0 + u];
        X[(long)(i0 + r) * ldx + (j0 + tx)] = acc;
    }
}

// ----------------------------------------------------------------------------
// Host orchestration (graph-capturable: kernel launches only).
// ----------------------------------------------------------------------------
extern "C" void kernel_launch(void* const* d_in, const int* in_sizes, int n_in,
                              void* d_out, int out_size)
{
    const float* x    = (const float*)d_in[0];
    const float* scal = (const float*)d_in[1];
    const float* pA   = (const float*)d_in[2];
    const float* pBp  = (const float*)d_in[3];
    const float* pBm  = (const float*)d_in[4];

    float* out  = (float*)d_out;
    float* flat = out + (size_t)NSIDE * NSIDE;

    float *bufA, *bufB;
    cudaGetSymbolAddress((void**)&bufA, g_bufA);
    cudaGetSymbolAddress((void**)&bufB, g_bufB);

    size_t levoff[6];
    size_t off = 0;
    {
        long t2 = 2048;
        for (int l = 0; l < 6; l++) { levoff[l] = off; off += 3ull * t2 * t2; t2 >>= 1; }
    }
    const size_t approxoff = off;

    // ---------------- forward ----------------
    const float* cur = x;
    long ldcur = NSIDE;
    int s = NSIDE;
    for (int lev = 0; lev < 6; lev++) {
        const int s2 = s >> 1;
        float* fb = flat + levoff[lev];
        float* ll; long ldll; int thr;
        if (lev == 5) { ll = flat + approxoff; ldll = 64; thr = 1; }
        else          { ll = (lev & 1) ? bufB : bufA; ldll = s2; thr = 0; }
        dim3 grd(s2 / 32, s2 / 32);
        fwd2d<<<grd, 256>>>(cur, s, ldcur, fb, ll, ldll, thr,
                            scal + lev * 8, scal + (lev + 1) * 8,
                            pA, pBp, pBm);
        cur = ll; ldcur = ldll; s = s2;
    }

    // ---------------- backward ----------------
    const float* aprev = flat + approxoff;
    long lda = 64;
    for (int lev = 5; lev >= 0; lev--) {
        const int s2 = 2048 >> lev;
        const int so = s2 * 2;
        const float* base = flat + levoff[lev];
        float* xo; long ldx;
        if (lev == 0) { xo = out; ldx = NSIDE; }
        else          { xo = (lev & 1) ? bufB : bufA; ldx = so; }
        dim3 grd(so / 64, so / 64);
        bwd2d<<<grd, 256>>>(base, aprev, lda, s2, xo, ldx,
                            scal + lev * 8, scal + (lev + 1) * 8);
        aprev = xo; lda = ldx;
    }
}

// round 3
// speedup vs baseline: 1.7709x; 1.0906x over previous
#include <cuda_runtime.h>

// ----------------------------------------------------------------------------
// Despawn2D: 6-level 2D db4 circular DWT + sigmoid threshold + inverse DWT.
// Fused per-level kernels, tile size templated per level so small levels
// still fill the 148-SM chip. N = 4096.
// d_out layout: [ recon (4096*4096) | flat coeffs (4096*4096) ]
// flat per level: (s2, 3*s2) row-major hh|hl|lh, then approx (64*64) last.
// ----------------------------------------------------------------------------

#define NSIDE 4096

__device__ float g_bufA[2048u * 2048u];   // ll ping (16 MB)
__device__ float g_bufB[2048u * 2048u];   // ll pong (16 MB)

__device__ __forceinline__ float thrf(float t, float a, float bp, float bm)
{
    float s1 = 1.0f / (1.0f + __expf(-a * (t - bp)));
    float s2 = 1.0f / (1.0f + __expf( a * (t + bm)));
    return t * (s1 + s2);
}

// ----------------------------------------------------------------------------
// Fused forward: TI x TI output tile per block (256 threads).
// Input window (circular halo): NW x NW, NW = 2*TI+6.
// Row conv -> sd/sa (NW x TI), col conv -> hh,hl,lh (thresholded) + ll.
// ----------------------------------------------------------------------------
template<int TI>
__global__ __launch_bounds__(256)
void fwd2d(const float* __restrict__ X, int s, long ldx,
           float* __restrict__ flatb,
           float* __restrict__ LL, long ldll, int thrLL,
           const float* __restrict__ hHp, const float* __restrict__ hVp,
           const float* __restrict__ pA, const float* __restrict__ pBp,
           const float* __restrict__ pBm)
{
    constexpr int NW = 2 * TI + 6;
    const int s2 = s >> 1;
    __shared__ float sx[NW][NW + 2];
    __shared__ float sd[NW][TI + 1];
    __shared__ float sa[NW][TI + 1];
    __shared__ float hH[8], wH[8], hV[8], wV[8];
    const int tid = threadIdx.x;
    if (tid < 8) { hH[tid] = hHp[tid]; hV[tid] = hVp[tid]; }
    __syncthreads();
    if (tid < 8) {
        wH[tid] = hH[7 - tid] * ((tid & 1) ? -1.0f : 1.0f);
        wV[tid] = hV[7 - tid] * ((tid & 1) ? -1.0f : 1.0f);
    }

    const int i0 = blockIdx.y * TI, j0 = blockIdx.x * TI;
    const int mask = s - 1;
    const int rb = 2 * i0 - 7, cb = 2 * j0 - 7;

    // load input window with circular wrap
    for (int t = tid; t < NW * NW; t += 256) {
        int rr = t / NW, cc = t - rr * NW;
        sx[rr][cc] = X[(long)((rb + rr) & mask) * ldx + ((cb + cc) & mask)];
    }
    __syncthreads();   // also publishes wH/wV

    // row conv: D[rr,j] over window sx[rr][2j+m]
    for (int t = tid; t < NW * TI; t += 256) {
        int rr = t / TI, j = t - rr * TI;
        float dv = 0.f, av = 0.f;
#pragma unroll
        for (int m = 0; m < 8; m++) {
            float xv = sx[rr][2 * j + m];
            dv += wH[7 - m] * xv;
            av += hH[7 - m] * xv;
        }
        sd[rr][j] = dv;
        sa[rr][j] = av;
    }
    __syncthreads();

    const float alpha = *pA, bp = *pBp, bm = *pBm;
    const long ldflat = 3L * s2;
    for (int t = tid; t < TI * TI; t += 256) {
        const int tx = t % TI, il = t / TI;
        const int i = i0 + il, j = j0 + tx;
        float hhv = 0.f, hlv = 0.f, lhv = 0.f, llv = 0.f;
#pragma unroll
        for (int m = 0; m < 8; m++) {
            float dv = sd[2 * il + m][tx];
            float av = sa[2 * il + m][tx];
            hhv += wV[7 - m] * dv;
            hlv += hV[7 - m] * dv;
            lhv += wV[7 - m] * av;
            llv += hV[7 - m] * av;
        }
        const long ro = (long)i * ldflat;
        flatb[ro + j]          = thrf(hhv, alpha, bp, bm);
        flatb[ro + s2 + j]     = thrf(hlv, alpha, bp, bm);
        flatb[ro + 2 * s2 + j] = thrf(lhv, alpha, bp, bm);
        LL[(long)i * ldll + j] = thrLL ? thrf(llv, alpha, bp, bm) : llv;
    }
}

// ----------------------------------------------------------------------------
// Fused backward: TO x TO output tile per block (256 threads).
// Coeff tiles NC x NC (NC = TO/2+4) of hh/hl/lh/approx with circular halo,
// column reconstruction -> sh/sl (TO x NC), then row reconstruction.
//   col: h[i,j] = sum_u wV[2u+q] hh[(i+q)/2+u, j] + hV[2u+q] hl[...]  (q=i&1)
//   row: x[r,i] = sum_u wH[2u+p] h[r,(i+p)/2+u] + hH[2u+p] l[...]     (p=i&1)
// ----------------------------------------------------------------------------
template<int TO>
__global__ __launch_bounds__(256)
void bwd2d(const float* __restrict__ base,   // hh | hl | lh, ld = 3*s2
           const float* __restrict__ ap, long lda,
           int s2,
           float* __restrict__ X, long ldx,
           const float* __restrict__ hHp, const float* __restrict__ hVp)
{
    constexpr int NC = TO / 2 + 4;
    __shared__ float shh[NC][NC + 1], shl[NC][NC + 1];
    __shared__ float slh[NC][NC + 1], sll[NC][NC + 1];
    __shared__ float sh[TO][NC + 1], sl[TO][NC + 1];
    __shared__ float hH[8], wH[8], hV[8], wV[8];
    const int tid = threadIdx.x;
    if (tid < 8) { hH[tid] = hHp[tid]; hV[tid] = hVp[tid]; }
    __syncthreads();
    if (tid < 8) {
        wH[tid] = hH[7 - tid] * ((tid & 1) ? -1.0f : 1.0f);
        wV[tid] = hV[7 - tid] * ((tid & 1) ? -1.0f : 1.0f);
    }

    const int i0 = blockIdx.y * TO, j0 = blockIdx.x * TO;
    const int mask = s2 - 1;
    const long ldc = 3L * s2;
    const int rb = i0 >> 1, cbb = j0 >> 1;

    for (int t = tid; t < NC * NC; t += 256) {
        int rr = t / NC, cc = t - rr * NC;
        int gr = (rb + rr) & mask, gc = (cbb + cc) & mask;
        long o = (long)gr * ldc + gc;
        shh[rr][cc] = base[o];
        shl[rr][cc] = base[o + s2];
        slh[rr][cc] = base[o + 2 * s2];
        sll[rr][cc] = ap[(long)gr * lda + gc];
    }
    __syncthreads();   // also publishes wH/wV

    // column reconstruction: TO local rows x NC local cols
    for (int t = tid; t < TO * NC; t += 256) {
        int r = t / NC, cc = t - r * NC;
        int q = r & 1;                 // i0 is even
        int m0 = (r + q) >> 1;
        float hv = 0.f, lv = 0.f;
#pragma unroll
        for (int u = 0; u < 4; u++) {
            float f1 = wV[2 * u + q], f2 = hV[2 * u + q];
            hv += f1 * shh[m0 + u][cc] + f2 * shl[m0 + u][cc];
            lv += f1 * slh[m0 + u][cc] + f2 * sll[m0 + u][cc];
        }
        sh[r][cc] = hv;
        sl[r][cc] = lv;
    }
    __syncthreads();

    // row reconstruction
    for (int t = tid; t < TO * TO; t += 256) {
        const int tx = t % TO, r = t / TO;
        const int p  = tx & 1;          // j0 is even
        const int m0 = (tx + p) >> 1;
        float acc = 0.f;
#pragma unroll
        for (int u = 0; u < 4; u++)
            acc += wH[2 * u + p] * sh[r][m0 + u]
                 + hH[2 * u + p] * sl[r][m0 + u];
        X[(long)(i0 + r) * ldx + (j0 + tx)] = acc;
    }
}

// ----------------------------------------------------------------------------
// Host orchestration (graph-capturable: kernel launches only).
// ----------------------------------------------------------------------------
extern "C" void kernel_launch(void* const* d_in, const int* in_sizes, int n_in,
                              void* d_out, int out_size)
{
    const float* x    = (const float*)d_in[0];
    const float* scal = (const float*)d_in[1];
    const float* pA   = (const float*)d_in[2];
    const float* pBp  = (const float*)d_in[3];
    const float* pBm  = (const float*)d_in[4];

    float* out  = (float*)d_out;
    float* flat = out + (size_t)NSIDE * NSIDE;

    float *bufA, *bufB;
    cudaGetSymbolAddress((void**)&bufA, g_bufA);
    cudaGetSymbolAddress((void**)&bufB, g_bufB);

    size_t levoff[6];
    size_t off = 0;
    {
        long t2 = 2048;
        for (int l = 0; l < 6; l++) { levoff[l] = off; off += 3ull * t2 * t2; t2 >>= 1; }
    }
    const size_t approxoff = off;

    // ---------------- forward ----------------
    const float* cur = x;
    long ldcur = NSIDE;
    int s = NSIDE;
    for (int lev = 0; lev < 6; lev++) {
        const int s2 = s >> 1;
        float* fb = flat + levoff[lev];
        float* ll; long ldll; int thr;
        if (lev == 5) { ll = flat + approxoff; ldll = 64; thr = 1; }
        else          { ll = (lev & 1) ? bufB : bufA; ldll = s2; thr = 0; }
        const float* hH = scal + lev * 8;
        const float* hV = scal + (lev + 1) * 8;
        if (s2 >= 512) {
            dim3 grd(s2 / 32, s2 / 32);
            fwd2d<32><<<grd, 256>>>(cur, s, ldcur, fb, ll, ldll, thr, hH, hV, pA, pBp, pBm);
        } else if (s2 >= 256) {
            dim3 grd(s2 / 16, s2 / 16);
            fwd2d<16><<<grd, 256>>>(cur, s, ldcur, fb, ll, ldll, thr, hH, hV, pA, pBp, pBm);
        } else {
            dim3 grd(s2 / 8, s2 / 8);
            fwd2d<8><<<grd, 256>>>(cur, s, ldcur, fb, ll, ldll, thr, hH, hV, pA, pBp, pBm);
        }
        cur = ll; ldcur = ldll; s = s2;
    }

    // ---------------- backward ----------------
    const float* aprev = flat + approxoff;
    long lda = 64;
    for (int lev = 5; lev >= 0; lev--) {
        const int s2 = 2048 >> lev;
        const int so = s2 * 2;
        const float* base = flat + levoff[lev];
        const float* hH = scal + lev * 8;
        const float* hV = scal + (lev + 1) * 8;
        float* xo; long ldx;
        if (lev == 0) { xo = out; ldx = NSIDE; }
        else          { xo = (lev & 1) ? bufB : bufA; ldx = so; }
        if (so >= 2048) {
            dim3 grd(so / 64, so / 64);
            bwd2d<64><<<grd, 256>>>(base, aprev, lda, s2, xo, ldx, hH, hV);
        } else if (so >= 512) {
            dim3 grd(so / 32, so / 32);
            bwd2d<32><<<grd, 256>>>(base, aprev, lda, s2, xo, ldx, hH, hV);
        } else {
            dim3 grd(so / 16, so / 16);
            bwd2d<16><<<grd, 256>>>(base, aprev, lda, s2, xo, ldx, hH, hV);
        }
        aprev = xo; lda = ldx;
    }
}

// round 4
// speedup vs baseline: 1.7831x; 1.0069x over previous
#include <cuda_runtime.h>

// ----------------------------------------------------------------------------
// Despawn2D: 6-level 2D db4 circular DWT + sigmoid threshold + inverse DWT.
// Big levels (0,1): one fused tiled kernel per level/direction.
// Small levels (2..5): ONE persistent kernel per direction with software
// grid barriers between levels (counters reset by init kernel per replay).
// d_out layout: [ recon (4096*4096) | flat coeffs (4096*4096) ]
// flat per level: (s2, 3*s2) row-major hh|hl|lh, then approx (64*64) last.
// ----------------------------------------------------------------------------

#define NSIDE 4096
#define NB_TAIL 512

__device__ float g_bufA[2048u * 2048u];   // ll ping (16 MB)
__device__ float g_bufB[2048u * 2048u];   // ll pong (16 MB)
__device__ unsigned g_barF;
__device__ unsigned g_barB;

__device__ __forceinline__ float thrf(float t, float a, float bp, float bm)
{
    float s1 = 1.0f / (1.0f + __expf(-a * (t - bp)));
    float s2 = 1.0f / (1.0f + __expf( a * (t + bm)));
    return t * (s1 + s2);
}

__device__ __forceinline__ void grid_barrier(unsigned* cnt, unsigned target)
{
    __syncthreads();
    if (threadIdx.x == 0) {
        __threadfence();
        atomicAdd(cnt, 1u);
        while (*((volatile unsigned*)cnt) < target) { }
        __threadfence();
    }
    __syncthreads();
}

__global__ void init_bars()
{
    g_barF = 0;
    g_barB = 0;
}

// ----------------------------------------------------------------------------
// Big fused forward (TI=32): 32x32 output tile, register-blocked col conv.
// ----------------------------------------------------------------------------
__global__ __launch_bounds__(256)
void fwd2d32(const float* __restrict__ X, int s, long ldx,
             float* __restrict__ flatb,
             float* __restrict__ LL, long ldll, int thrLL,
             const float* __restrict__ hHp, const float* __restrict__ hVp,
             const float* __restrict__ pA, const float* __restrict__ pBp,
             const float* __restrict__ pBm)
{
    __shared__ float sx[70][72];
    __shared__ float sd[70][33];
    __shared__ float sa[70][33];
    __shared__ float hH[8], wH[8], hV[8], wV[8];
    const int tid = threadIdx.x;
    if (tid < 8) { hH[tid] = hHp[tid]; hV[tid] = hVp[tid]; }
    __syncthreads();
    if (tid < 8) {
        wH[tid] = hH[7 - tid] * ((tid & 1) ? -1.0f : 1.0f);
        wV[tid] = hV[7 - tid] * ((tid & 1) ? -1.0f : 1.0f);
    }

    const int s2 = s >> 1;
    const int i0 = blockIdx.y << 5, j0 = blockIdx.x << 5;
    const int mask = s - 1;
    const int rb = 2 * i0 - 7, cb = 2 * j0 - 7;

    for (int t = tid; t < 70 * 70; t += 256) {
        int rr = t / 70, cc = t - rr * 70;
        sx[rr][cc] = X[(long)((rb + rr) & mask) * ldx + ((cb + cc) & mask)];
    }
    __syncthreads();   // publishes wH/wV too

    // row conv: 2 adjacent outputs per iteration (10-wide window)
    for (int t = tid; t < 70 * 16; t += 256) {
        int rr = t >> 4, jp = t & 15;
        float xx[10];
#pragma unroll
        for (int m = 0; m < 10; m++) xx[m] = sx[rr][4 * jp + m];
        float d0 = 0.f, a0 = 0.f, d1 = 0.f, a1 = 0.f;
#pragma unroll
        for (int m = 0; m < 8; m++) {
            float cw = wH[7 - m], ch = hH[7 - m];
            d0 += cw * xx[m];     a0 += ch * xx[m];
            d1 += cw * xx[m + 2]; a1 += ch * xx[m + 2];
        }
        sd[rr][2 * jp] = d0; sd[rr][2 * jp + 1] = d1;
        sa[rr][2 * jp] = a0; sa[rr][2 * jp + 1] = a1;
    }
    __syncthreads();

    // col conv: 4 contiguous output rows per thread via 14-row register window
    const float alpha = *pA, bp = *pBp, bm = *pBm;
    const int tx = tid & 31, ty = tid >> 5;
    const int j = j0 + tx;
    const long ldflat = 3L * s2;
    float dvv[14], avv[14];
#pragma unroll
    for (int m = 0; m < 14; m++) {
        dvv[m] = sd[8 * ty + m][tx];
        avv[m] = sa[8 * ty + m][tx];
    }
#pragma unroll
    for (int k = 0; k < 4; k++) {
        float hhv = 0.f, hlv = 0.f, lhv = 0.f, llv = 0.f;
#pragma unroll
        for (int m = 0; m < 8; m++) {
            float dv = dvv[2 * k + m], av = avv[2 * k + m];
            float cw = wV[7 - m], ch = hV[7 - m];
            hhv += cw * dv; hlv += ch * dv;
            lhv += cw * av; llv += ch * av;
        }
        const int i = i0 + 4 * ty + k;
        const long ro = (long)i * ldflat;
        flatb[ro + j]          = thrf(hhv, alpha, bp, bm);
        flatb[ro + s2 + j]     = thrf(hlv, alpha, bp, bm);
        flatb[ro + 2 * s2 + j] = thrf(lhv, alpha, bp, bm);
        LL[(long)i * ldll + j] = thrLL ? thrf(llv, alpha, bp, bm) : llv;
    }
}

// ----------------------------------------------------------------------------
// Big fused backward (TO=64): paired row reconstruction + float2 stores.
// ----------------------------------------------------------------------------
__global__ __launch_bounds__(256)
void bwd2d64(const float* __restrict__ base,   // hh | hl | lh, ld = 3*s2
             const float* __restrict__ ap, long lda,
             int s2,
             float* __restrict__ X, long ldx,
             const float* __restrict__ hHp, const float* __restrict__ hVp)
{
    __shared__ float shh[36][37], shl[36][37], slh[36][37], sll[36][37];
    __shared__ float sh[64][37], sl[64][37];
    __shared__ float hH[8], wH[8], hV[8], wV[8];
    const int tid = threadIdx.x;
    if (tid < 8) { hH[tid] = hHp[tid]; hV[tid] = hVp[tid]; }
    __syncthreads();
    if (tid < 8) {
        wH[tid] = hH[7 - tid] * ((tid & 1) ? -1.0f : 1.0f);
        wV[tid] = hV[7 - tid] * ((tid & 1) ? -1.0f : 1.0f);
    }

    const int i0 = blockIdx.y << 6, j0 = blockIdx.x << 6;
    const int mask = s2 - 1;
    const long ldc = 3L * s2;
    const int rbb = i0 >> 1, cbb = j0 >> 1;

    for (int t = tid; t < 36 * 36; t += 256) {
        int rr = t / 36, cc = t - rr * 36;
        int gr = (rbb + rr) & mask, gc = (cbb + cc) & mask;
        long o = (long)gr * ldc + gc;
        shh[rr][cc] = base[o];
        shl[rr][cc] = base[o + s2];
        slh[rr][cc] = base[o + 2 * s2];
        sll[rr][cc] = ap[(long)gr * lda + gc];
    }
    __syncthreads();   // publishes wH/wV too

    for (int t = tid; t < 64 * 36; t += 256) {
        int r = t / 36, cc = t - r * 36;
        int q = r & 1;
        int m0 = (r + q) >> 1;
        float hv = 0.f, lv = 0.f;
#pragma unroll
        for (int u = 0; u < 4; u++) {
            float f1 = wV[2 * u + q], f2 = hV[2 * u + q];
            hv += f1 * shh[m0 + u][cc] + f2 * shl[m0 + u][cc];
            lv += f1 * slh[m0 + u][cc] + f2 * sll[m0 + u][cc];
        }
        sh[r][cc] = hv;
        sl[r][cc] = lv;
    }
    __syncthreads();

    // row reconstruction: even/odd pair shares 5-tap window
    const int tx2 = tid & 31, ty = tid >> 5;
#pragma unroll
    for (int k = 0; k < 8; k++) {
        const int r = ty + 8 * k;
        float a0 = sh[r][tx2], a1 = sh[r][tx2 + 1], a2 = sh[r][tx2 + 2],
              a3 = sh[r][tx2 + 3], a4 = sh[r][tx2 + 4];
        float b0 = sl[r][tx2], b1 = sl[r][tx2 + 1], b2 = sl[r][tx2 + 2],
              b3 = sl[r][tx2 + 3], b4 = sl[r][tx2 + 4];
        float2 v;
        v.x = wH[0] * a0 + wH[2] * a1 + wH[4] * a2 + wH[6] * a3
            + hH[0] * b0 + hH[2] * b1 + hH[4] * b2 + hH[6] * b3;
        v.y = wH[1] * a1 + wH[3] * a2 + wH[5] * a3 + wH[7] * a4
            + hH[1] * b1 + hH[3] * b2 + hH[5] * b3 + hH[7] * b4;
        *(float2*)&X[(long)(i0 + r) * ldx + (j0 + 2 * tx2)] = v;
    }
}

// ----------------------------------------------------------------------------
// Tail device functions (tile loops inside a persistent kernel).
// ----------------------------------------------------------------------------
template<int TI>
__device__ void fwd_tiles(float* pool,
                          const float* __restrict__ X, int s, long ldx,
                          float* __restrict__ flatb,
                          float* __restrict__ LL, long ldll, int thrLL,
                          const float* hH, const float* wH,
                          const float* hV, const float* wV,
                          float alpha, float bp, float bm, int nb)
{
    constexpr int NW = 2 * TI + 6;
    constexpr int LDW = NW + 2;
    float (*sx)[LDW]    = reinterpret_cast<float(*)[LDW]>(pool);
    float (*sd)[TI + 1] = reinterpret_cast<float(*)[TI + 1]>(pool + NW * LDW);
    float (*sa)[TI + 1] = reinterpret_cast<float(*)[TI + 1]>(pool + NW * LDW + NW * (TI + 1));
    const int s2 = s >> 1;
    const int nt = s2 / TI;
    const int mask = s - 1;
    const int tid = threadIdx.x;
    const long ldflat = 3L * s2;

    for (int tile = blockIdx.x; tile < nt * nt; tile += nb) {
        const int by = tile / nt, bx = tile - by * nt;
        const int i0 = by * TI, j0 = bx * TI;
        const int rb = 2 * i0 - 7, cb = 2 * j0 - 7;
        for (int t = tid; t < NW * NW; t += 256) {
            int rr = t / NW, cc = t - rr * NW;
            sx[rr][cc] = X[(long)((rb + rr) & mask) * ldx + ((cb + cc) & mask)];
        }
        __syncthreads();
        for (int t = tid; t < NW * TI; t += 256) {
            int rr = t / TI, jj = t - rr * TI;
            float dv = 0.f, av = 0.f;
#pragma unroll
            for (int m = 0; m < 8; m++) {
                float xv = sx[rr][2 * jj + m];
                dv += wH[7 - m] * xv;
                av += hH[7 - m] * xv;
            }
            sd[rr][jj] = dv;
            sa[rr][jj] = av;
        }
        __syncthreads();
        for (int t = tid; t < TI * TI; t += 256) {
            const int tx = t % TI, il = t / TI;
            const int i = i0 + il, j = j0 + tx;
            float hhv = 0.f, hlv = 0.f, lhv = 0.f, llv = 0.f;
#pragma unroll
            for (int m = 0; m < 8; m++) {
                float dv = sd[2 * il + m][tx];
                float av = sa[2 * il + m][tx];
                hhv += wV[7 - m] * dv; hlv += hV[7 - m] * dv;
                lhv += wV[7 - m] * av; llv += hV[7 - m] * av;
            }
            const long ro = (long)i * ldflat;
            flatb[ro + j]          = thrf(hhv, alpha, bp, bm);
            flatb[ro + s2 + j]     = thrf(hlv, alpha, bp, bm);
            flatb[ro + 2 * s2 + j] = thrf(lhv, alpha, bp, bm);
            LL[(long)i * ldll + j] = thrLL ? thrf(llv, alpha, bp, bm) : llv;
        }
        __syncthreads();
    }
}

template<int TO>
__device__ void bwd_tiles(float* pool,
                          const float* __restrict__ base,
                          const float* __restrict__ ap, long lda,
                          int s2, float* __restrict__ X, long ldx,
                          const float* hH, const float* wH,
                          const float* hV, const float* wV, int nb)
{
    constexpr int NC = TO / 2 + 4;
    constexpr int LDC = NC + 1;
    float (*shh)[LDC] = reinterpret_cast<float(*)[LDC]>(pool);
    float (*shl)[LDC] = reinterpret_cast<float(*)[LDC]>(pool + NC * LDC);
    float (*slh)[LDC] = reinterpret_cast<float(*)[LDC]>(pool + 2 * NC * LDC);
    float (*sll)[LDC] = reinterpret_cast<float(*)[LDC]>(pool + 3 * NC * LDC);
    float (*sh)[LDC]  = reinterpret_cast<float(*)[LDC]>(pool + 4 * NC * LDC);
    float (*sl)[LDC]  = reinterpret_cast<float(*)[LDC]>(pool + 4 * NC * LDC + TO * LDC);
    const int nt = (2 * s2) / TO;
    const int mask = s2 - 1;
    const long ldc = 3L * s2;
    const int tid = threadIdx.x;

    for (int tile = blockIdx.x; tile < nt * nt; tile += nb) {
        const int by = tile / nt, bx = tile - by * nt;
        const int i0 = by * TO, j0 = bx * TO;
        const int rbb = i0 >> 1, cbb = j0 >> 1;
        for (int t = tid; t < NC * NC; t += 256) {
            int rr = t / NC, cc = t - rr * NC;
            int gr = (rbb + rr) & mask, gc = (cbb + cc) & mask;
            long o = (long)gr * ldc + gc;
            shh[rr][cc] = base[o];
            shl[rr][cc] = base[o + s2];
            slh[rr][cc] = base[o + 2 * s2];
            sll[rr][cc] = ap[(long)gr * lda + gc];
        }
        __syncthreads();
        for (int t = tid; t < TO * NC; t += 256) {
            int r = t / NC, cc = t - r * NC;
            int q = r & 1;
            int m0 = (r + q) >> 1;
            float hv = 0.f, lv = 0.f;
#pragma unroll
            for (int u = 0; u < 4; u++) {
                float f1 = wV[2 * u + q], f2 = hV[2 * u + q];
                hv += f1 * shh[m0 + u][cc] + f2 * shl[m0 + u][cc];
                lv += f1 * slh[m0 + u][cc] + f2 * sll[m0 + u][cc];
            }
            sh[r][cc] = hv;
            sl[r][cc] = lv;
        }
        __syncthreads();
        for (int t = tid; t < TO * TO; t += 256) {
            const int tx = t % TO, r = t / TO;
            const int p  = tx & 1;
            const int m0 = (tx + p) >> 1;
            float acc = 0.f;
#pragma unroll
            for (int u = 0; u < 4; u++)
                acc += wH[2 * u + p] * sh[r][m0 + u]
                     + hH[2 * u + p] * sl[r][m0 + u];
            X[(long)(i0 + r) * ldx + (j0 + tx)] = acc;
        }
        __syncthreads();
    }
}

// ----------------------------------------------------------------------------
// Persistent tail kernels. All NB_TAIL blocks are guaranteed co-resident
// (__launch_bounds__(256,4): 4 blocks/SM x 148 SMs = 592 >= 512).
// ----------------------------------------------------------------------------
__global__ __launch_bounds__(256, 4)
void fwd_tail(const float* __restrict__ llin,     // lev1 ll (1024x1024)
              float* bufA, float* bufB, float* flat,
              const float* __restrict__ scal,
              const float* pA, const float* pBp, const float* pBm)
{
    __shared__ float pool[2816];
    __shared__ float hH[8], wH[8], hV[8], wV[8];
    const float alpha = *pA, bp = *pBp, bm = *pBm;
    const int tid = threadIdx.x;
    const int nb = gridDim.x;
    const size_t levoff[6] = {0, 12582912, 15728640, 16515072, 16711680, 16760832};

    const float* cur = llin;
    long ldcur = 1024;
    int s = 1024;
    unsigned bc = 0;
    for (int lev = 2; lev <= 5; lev++) {
        if (tid < 8) { hH[tid] = scal[lev * 8 + tid]; hV[tid] = scal[(lev + 1) * 8 + tid]; }
        __syncthreads();
        if (tid < 8) {
            wH[tid] = hH[7 - tid] * ((tid & 1) ? -1.0f : 1.0f);
            wV[tid] = hV[7 - tid] * ((tid & 1) ? -1.0f : 1.0f);
        }
        __syncthreads();
        const int s2 = s >> 1;
        float* fb = flat + levoff[lev];
        float* ll; long ldll; int thr;
        if (lev == 5) { ll = flat + 16773120; ldll = 64; thr = 1; }
        else          { ll = (lev & 1) ? bufB : bufA; ldll = s2; thr = 0; }
        if (s2 >= 256)
            fwd_tiles<16>(pool, cur, s, ldcur, fb, ll, ldll, thr, hH, wH, hV, wV, alpha, bp, bm, nb);
        else
            fwd_tiles<8>(pool, cur, s, ldcur, fb, ll, ldll, thr, hH, wH, hV, wV, alpha, bp, bm, nb);
        cur = ll; ldcur = ldll; s = s2;
        if (lev < 5) { bc++; grid_barrier(&g_barF, bc * (unsigned)nb); }
    }
}

__global__ __launch_bounds__(256, 4)
void bwd_tail(float* bufA, float* bufB, float* flat,
              const float* __restrict__ scal)
{
    __shared__ float pool[3072];
    __shared__ float hH[8], wH[8], hV[8], wV[8];
    const int tid = threadIdx.x;
    const int nb = gridDim.x;
    const size_t levoff[6] = {0, 12582912, 15728640, 16515072, 16711680, 16760832};

    const float* aprev = flat + 16773120;
    long lda = 64;
    unsigned bc = 0;
    for (int lev = 5; lev >= 2; lev--) {
        if (tid < 8) { hH[tid] = scal[lev * 8 + tid]; hV[tid] = scal[(lev + 1) * 8 + tid]; }
        __syncthreads();
        if (tid < 8) {
            wH[tid] = hH[7 - tid] * ((tid & 1) ? -1.0f : 1.0f);
            wV[tid] = hV[7 - tid] * ((tid & 1) ? -1.0f : 1.0f);
        }
        __syncthreads();
        const int s2 = 2048 >> lev;
        const int so = 2 * s2;
        const float* base = flat + levoff[lev];
        float* xo = (lev & 1) ? bufB : bufA;
        long ldx = so;
        if (so >= 512)
            bwd_tiles<32>(pool, base, aprev, lda, s2, xo, ldx, hH, wH, hV, wV, nb);
        else
            bwd_tiles<16>(pool, base, aprev, lda, s2, xo, ldx, hH, wH, hV, wV, nb);
        aprev = xo; lda = ldx;
        if (lev > 2) { bc++; grid_barrier(&g_barB, bc * (unsigned)nb); }
    }
}

// ----------------------------------------------------------------------------
// Host orchestration (graph-capturable: kernel launches only).
// ----------------------------------------------------------------------------
extern "C" void kernel_launch(void* const* d_in, const int* in_sizes, int n_in,
                              void* d_out, int out_size)
{
    const float* x    = (const float*)d_in[0];
    const float* scal = (const float*)d_in[1];
    const float* pA   = (const float*)d_in[2];
    const float* pBp  = (const float*)d_in[3];
    const float* pBm  = (const float*)d_in[4];

    float* out  = (float*)d_out;
    float* flat = out + (size_t)NSIDE * NSIDE;

    float *bufA, *bufB;
    cudaGetSymbolAddress((void**)&bufA, g_bufA);
    cudaGetSymbolAddress((void**)&bufB, g_bufB);

    init_bars<<<1, 1>>>();

    // forward level 0: x (4096) -> flat lev0 + bufA (2048)
    fwd2d32<<<dim3(64, 64), 256>>>(x, 4096, 4096,
                                   flat, bufA, 2048, 0,
                                   scal, scal + 8, pA, pBp, pBm);
    // forward level 1: bufA (2048) -> flat lev1 + bufB (1024)
    fwd2d32<<<dim3(32, 32), 256>>>(bufA, 2048, 2048,
                                   flat + 12582912, bufB, 1024, 0,
                                   scal + 8, scal + 16, pA, pBp, pBm);
    // forward levels 2..5 (persistent)
    fwd_tail<<<NB_TAIL, 256>>>(bufB, bufA, bufB, flat, scal, pA, pBp, pBm);

    // backward levels 5..2 (persistent) -> bufA (1024)
    bwd_tail<<<NB_TAIL, 256>>>(bufA, bufB, flat, scal);

    // backward level 1: coeffs lev1 + bufA (1024) -> bufB (2048)
    bwd2d64<<<dim3(32, 32), 256>>>(flat + 12582912, bufA, 1024,
                                   1024, bufB, 2048,
                                   scal + 8, scal + 16);
    // backward level 0: coeffs lev0 + bufB (2048) -> out (4096)
    bwd2d64<<<dim3(64, 64), 256>>>(flat, bufB, 2048,
                                   2048, out, 4096,
                                   scal, scal + 8);
}

// round 5
// speedup vs baseline: 2.2460x; 1.2596x over previous
#include <cuda_runtime.h>

// ----------------------------------------------------------------------------
// Despawn2D: 6-level 2D db4 circular DWT + sigmoid threshold + inverse DWT.
// Levels 0,1: fused tiled kernels with unrolled high-MLP load loops.
// Levels 2..5 fwd + 5..2 bwd: ONE persistent kernel with grid barriers.
// d_out layout: [ recon (4096*4096) | flat coeffs (4096*4096) ]
// flat per level: (s2, 3*s2) row-major hh|hl|lh, then approx (64*64) last.
// ----------------------------------------------------------------------------

#define NSIDE 4096
#define NB_TAIL 512

__device__ float g_bufA[2048u * 2048u];   // ll ping (16 MB)
__device__ float g_bufB[2048u * 2048u];   // ll pong (16 MB)
__device__ unsigned g_bar;

__global__ void init_bars() { g_bar = 0; }

__device__ __forceinline__ float thrf(float t, float a, float bp, float bm)
{
    float s1 = 1.0f / (1.0f + __expf(-a * (t - bp)));
    float s2 = 1.0f / (1.0f + __expf( a * (t + bm)));
    return t * (s1 + s2);
}

__device__ __forceinline__ void grid_barrier(unsigned* cnt, unsigned target)
{
    __syncthreads();
    if (threadIdx.x == 0) {
        __threadfence();
        atomicAdd(cnt, 1u);
        while (*((volatile unsigned*)cnt) < target) { }
        __threadfence();
    }
    __syncthreads();
}

// ----------------------------------------------------------------------------
// Big fused forward (TI=32). Unrolled warp-per-row global loads (high MLP).
// ----------------------------------------------------------------------------
__global__ __launch_bounds__(256)
void fwd2d32(const float* __restrict__ X, int s, long ldx,
             float* __restrict__ flatb,
             float* __restrict__ LL, long ldll, int thrLL,
             const float* __restrict__ hHp, const float* __restrict__ hVp,
             const float* __restrict__ pA, const float* __restrict__ pBp,
             const float* __restrict__ pBm)
{
    __shared__ float sx[70][72];
    __shared__ float sd[70][33];
    __shared__ float sa[70][33];
    __shared__ float hH[8], wH[8], hV[8], wV[8];
    const int tid = threadIdx.x;
    const int wid = tid >> 5, lane = tid & 31;
    if (tid < 8) { hH[tid] = hHp[tid]; hV[tid] = hVp[tid]; }
    __syncthreads();
    if (tid < 8) {
        wH[tid] = hH[7 - tid] * ((tid & 1) ? -1.0f : 1.0f);
        wV[tid] = hV[7 - tid] * ((tid & 1) ? -1.0f : 1.0f);
    }

    const int s2 = s >> 1;
    const int i0 = blockIdx.y << 5, j0 = blockIdx.x << 5;
    const int mask = s - 1;
    const int rb = 2 * i0 - 7, cb = 2 * j0 - 7;

    // unrolled load: warp w -> rows w, w+8, ..., lanes stride cols (27 slots)
#pragma unroll
    for (int k = 0; k < 9; k++) {
        const int rr = wid + 8 * k;
        if (rr < 70) {
            const float* xr = X + (long)((rb + rr) & mask) * ldx;
#pragma unroll
            for (int cc = 0; cc < 3; cc++) {
                const int c = lane + 32 * cc;
                if (c < 70) sx[rr][c] = xr[(cb + c) & mask];
            }
        }
    }
    __syncthreads();   // publishes wH/wV too

    // row conv: 2 adjacent outputs per iteration (10-wide window)
#pragma unroll
    for (int k = 0; k < 5; k++) {
        const int t = tid + 256 * k;
        if (t < 70 * 16) {
            const int rr = t >> 4, jp = t & 15;
            float xx[10];
#pragma unroll
            for (int m = 0; m < 10; m++) xx[m] = sx[rr][4 * jp + m];
            float d0 = 0.f, a0 = 0.f, d1 = 0.f, a1 = 0.f;
#pragma unroll
            for (int m = 0; m < 8; m++) {
                float cw = wH[7 - m], ch = hH[7 - m];
                d0 += cw * xx[m];     a0 += ch * xx[m];
                d1 += cw * xx[m + 2]; a1 += ch * xx[m + 2];
            }
            sd[rr][2 * jp] = d0; sd[rr][2 * jp + 1] = d1;
            sa[rr][2 * jp] = a0; sa[rr][2 * jp + 1] = a1;
        }
    }
    __syncthreads();

    // col conv: 4 contiguous output rows per thread via 14-row register window
    const float alpha = *pA, bp = *pBp, bm = *pBm;
    const int tx = lane;
    const int ty = wid;
    const int j = j0 + tx;
    const long ldflat = 3L * s2;
    float dvv[14], avv[14];
#pragma unroll
    for (int m = 0; m < 14; m++) {
        dvv[m] = sd[8 * ty + m][tx];
        avv[m] = sa[8 * ty + m][tx];
    }
#pragma unroll
    for (int k = 0; k < 4; k++) {
        float hhv = 0.f, hlv = 0.f, lhv = 0.f, llv = 0.f;
#pragma unroll
        for (int m = 0; m < 8; m++) {
            float dv = dvv[2 * k + m], av = avv[2 * k + m];
            float cw = wV[7 - m], ch = hV[7 - m];
            hhv += cw * dv; hlv += ch * dv;
            lhv += cw * av; llv += ch * av;
        }
        const int i = i0 + 4 * ty + k;
        const long ro = (long)i * ldflat;
        flatb[ro + j]          = thrf(hhv, alpha, bp, bm);
        flatb[ro + s2 + j]     = thrf(hlv, alpha, bp, bm);
        flatb[ro + 2 * s2 + j] = thrf(lhv, alpha, bp, bm);
        LL[(long)i * ldll + j] = thrLL ? thrf(llv, alpha, bp, bm) : llv;
    }
}

// ----------------------------------------------------------------------------
// Big fused backward (TO=64). Unrolled 4-stream loads, paired row recon.
// ----------------------------------------------------------------------------
__global__ __launch_bounds__(256)
void bwd2d64(const float* __restrict__ base,   // hh | hl | lh, ld = 3*s2
             const float* __restrict__ ap, long lda,
             int s2,
             float* __restrict__ X, long ldx,
             const float* __restrict__ hHp, const float* __restrict__ hVp)
{
    __shared__ float shh[36][37], shl[36][37], slh[36][37], sll[36][37];
    __shared__ float sh[64][37], sl[64][37];
    __shared__ float hH[8], wH[8], hV[8], wV[8];
    const int tid = threadIdx.x;
    const int wid = tid >> 5, lane = tid & 31;
    if (tid < 8) { hH[tid] = hHp[tid]; hV[tid] = hVp[tid]; }
    __syncthreads();
    if (tid < 8) {
        wH[tid] = hH[7 - tid] * ((tid & 1) ? -1.0f : 1.0f);
        wV[tid] = hV[7 - tid] * ((tid & 1) ? -1.0f : 1.0f);
    }

    const int i0 = blockIdx.y << 6, j0 = blockIdx.x << 6;
    const int mask = s2 - 1;
    const long ldc = 3L * s2;
    const int rbb = i0 >> 1, cbb = j0 >> 1;

#pragma unroll
    for (int k = 0; k < 5; k++) {
        const int rr = wid + 8 * k;
        if (rr < 36) {
            const int gr = (rbb + rr) & mask;
            const long o  = (long)gr * ldc;
            const long oa = (long)gr * lda;
#pragma unroll
            for (int cc = 0; cc < 2; cc++) {
                const int c = lane + 32 * cc;
                if (c < 36) {
                    const int gc = (cbb + c) & mask;
                    shh[rr][c] = base[o + gc];
                    shl[rr][c] = base[o + s2 + gc];
                    slh[rr][c] = base[o + 2 * s2 + gc];
                    sll[rr][c] = ap[oa + gc];
                }
            }
        }
    }
    __syncthreads();   // publishes wH/wV too

#pragma unroll
    for (int k = 0; k < 9; k++) {
        const int t = tid + 256 * k;
        if (t < 64 * 36) {
            const int r = t / 36, cc = t - r * 36;
            const int q = r & 1;
            const int m0 = (r + q) >> 1;
            float hv = 0.f, lv = 0.f;
#pragma unroll
            for (int u = 0; u < 4; u++) {
                float f1 = wV[2 * u + q], f2 = hV[2 * u + q];
                hv += f1 * shh[m0 + u][cc] + f2 * shl[m0 + u][cc];
                lv += f1 * slh[m0 + u][cc] + f2 * sll[m0 + u][cc];
            }
            sh[r][cc] = hv;
            sl[r][cc] = lv;
        }
    }
    __syncthreads();

    // row reconstruction: even/odd pair shares 5-tap window, float2 stores
#pragma unroll
    for (int k = 0; k < 8; k++) {
        const int r = wid + 8 * k;
        float a0 = sh[r][lane], a1 = sh[r][lane + 1], a2 = sh[r][lane + 2],
              a3 = sh[r][lane + 3], a4 = sh[r][lane + 4];
        float b0 = sl[r][lane], b1 = sl[r][lane + 1], b2 = sl[r][lane + 2],
              b3 = sl[r][lane + 3], b4 = sl[r][lane + 4];
        float2 v;
        v.x = wH[0] * a0 + wH[2] * a1 + wH[4] * a2 + wH[6] * a3
            + hH[0] * b0 + hH[2] * b1 + hH[4] * b2 + hH[6] * b3;
        v.y = wH[1] * a1 + wH[3] * a2 + wH[5] * a3 + wH[7] * a4
            + hH[1] * b1 + hH[3] * b2 + hH[5] * b3 + hH[7] * b4;
        *(float2*)&X[(long)(i0 + r) * ldx + (j0 + 2 * lane)] = v;
    }
}

// ----------------------------------------------------------------------------
// Tail device functions (constexpr-unrolled tile loops).
// ----------------------------------------------------------------------------
template<int TI>
__device__ void fwd_tiles(float* pool,
                          const float* __restrict__ X, int s, long ldx,
                          float* __restrict__ flatb,
                          float* __restrict__ LL, long ldll, int thrLL,
                          const float* hH, const float* wH,
                          const float* hV, const float* wV,
                          float alpha, float bp, float bm, int nb)
{
    constexpr int NW = 2 * TI + 6;
    constexpr int LDW = NW + 2;
    float (*sx)[LDW]    = reinterpret_cast<float(*)[LDW]>(pool);
    float (*sd)[TI + 1] = reinterpret_cast<float(*)[TI + 1]>(pool + NW * LDW);
    float (*sa)[TI + 1] = reinterpret_cast<float(*)[TI + 1]>(pool + NW * LDW + NW * (TI + 1));
    const int s2 = s >> 1;
    const int nt = s2 / TI;
    const int mask = s - 1;
    const int tid = threadIdx.x;
    const long ldflat = 3L * s2;
    constexpr int NL1 = (NW * NW + 255) / 256;
    constexpr int NL2 = (NW * TI + 255) / 256;
    constexpr int NL3 = (TI * TI + 255) / 256;

    for (int tile = blockIdx.x; tile < nt * nt; tile += nb) {
        const int by = tile / nt, bx = tile - by * nt;
        const int i0 = by * TI, j0 = bx * TI;
        const int rb = 2 * i0 - 7, cb = 2 * j0 - 7;
#pragma unroll
        for (int k = 0; k < NL1; k++) {
            const int t = tid + 256 * k;
            if (t < NW * NW) {
                const int rr = t / NW, cc = t - rr * NW;
                sx[rr][cc] = X[(long)((rb + rr) & mask) * ldx + ((cb + cc) & mask)];
            }
        }
        __syncthreads();
#pragma unroll
        for (int k = 0; k < NL2; k++) {
            const int t = tid + 256 * k;
            if (t < NW * TI) {
                const int rr = t / TI, jj = t - rr * TI;
                float dv = 0.f, av = 0.f;
#pragma unroll
                for (int m = 0; m < 8; m++) {
                    float xv = sx[rr][2 * jj + m];
                    dv += wH[7 - m] * xv;
                    av += hH[7 - m] * xv;
                }
                sd[rr][jj] = dv;
                sa[rr][jj] = av;
            }
        }
        __syncthreads();
#pragma unroll
        for (int k = 0; k < NL3; k++) {
            const int t = tid + 256 * k;
            if (t < TI * TI) {
                const int tx = t % TI, il = t / TI;
                const int i = i0 + il, j = j0 + tx;
                float hhv = 0.f, hlv = 0.f, lhv = 0.f, llv = 0.f;
#pragma unroll
                for (int m = 0; m < 8; m++) {
                    float dv = sd[2 * il + m][tx];
                    float av = sa[2 * il + m][tx];
                    hhv += wV[7 - m] * dv; hlv += hV[7 - m] * dv;
                    lhv += wV[7 - m] * av; llv += hV[7 - m] * av;
                }
                const long ro = (long)i * ldflat;
                flatb[ro + j]          = thrf(hhv, alpha, bp, bm);
                flatb[ro + s2 + j]     = thrf(hlv, alpha, bp, bm);
                flatb[ro + 2 * s2 + j] = thrf(lhv, alpha, bp, bm);
                LL[(long)i * ldll + j] = thrLL ? thrf(llv, alpha, bp, bm) : llv;
            }
        }
        __syncthreads();
    }
}

template<int TO>
__device__ void bwd_tiles(float* pool,
                          const float* __restrict__ base,
                          const float* __restrict__ ap, long lda,
                          int s2, float* __restrict__ X, long ldx,
                          const float* hH, const float* wH,
                          const float* hV, const float* wV, int nb)
{
    constexpr int NC = TO / 2 + 4;
    constexpr int LDC = NC + 1;
    float (*shh)[LDC] = reinterpret_cast<float(*)[LDC]>(pool);
    float (*shl)[LDC] = reinterpret_cast<float(*)[LDC]>(pool + NC * LDC);
    float (*slh)[LDC] = reinterpret_cast<float(*)[LDC]>(pool + 2 * NC * LDC);
    float (*sll)[LDC] = reinterpret_cast<float(*)[LDC]>(pool + 3 * NC * LDC);
    float (*sh)[LDC]  = reinterpret_cast<float(*)[LDC]>(pool + 4 * NC * LDC);
    float (*sl)[LDC]  = reinterpret_cast<float(*)[LDC]>(pool + 4 * NC * LDC + TO * LDC);
    const int nt = (2 * s2) / TO;
    const int mask = s2 - 1;
    const long ldc = 3L * s2;
    const int tid = threadIdx.x;
    constexpr int NL1 = (NC * NC + 255) / 256;
    constexpr int NL2 = (TO * NC + 255) / 256;
    constexpr int NL3 = (TO * TO + 255) / 256;

    for (int tile = blockIdx.x; tile < nt * nt; tile += nb) {
        const int by = tile / nt, bx = tile - by * nt;
        const int i0 = by * TO, j0 = bx * TO;
        const int rbb = i0 >> 1, cbb = j0 >> 1;
#pragma unroll
        for (int k = 0; k < NL1; k++) {
            const int t = tid + 256 * k;
            if (t < NC * NC) {
                const int rr = t / NC, cc = t - rr * NC;
                const int gr = (rbb + rr) & mask, gc = (cbb + cc) & mask;
                const long o = (long)gr * ldc + gc;
                shh[rr][cc] = base[o];
                shl[rr][cc] = base[o + s2];
                slh[rr][cc] = base[o + 2 * s2];
                sll[rr][cc] = ap[(long)gr * lda + gc];
            }
        }
        __syncthreads();
#pragma unroll
        for (int k = 0; k < NL2; k++) {
            const int t = tid + 256 * k;
            if (t < TO * NC) {
                const int r = t / NC, cc = t - r * NC;
                const int q = r & 1;
                const int m0 = (r + q) >> 1;
                float hv = 0.f, lv = 0.f;
#pragma unroll
                for (int u = 0; u < 4; u++) {
                    float f1 = wV[2 * u + q], f2 = hV[2 * u + q];
                    hv += f1 * shh[m0 + u][cc] + f2 * shl[m0 + u][cc];
                    lv += f1 * slh[m0 + u][cc] + f2 * sll[m0 + u][cc];
                }
                sh[r][cc] = hv;
                sl[r][cc] = lv;
            }
        }
        __syncthreads();
#pragma unroll
        for (int k = 0; k < NL3; k++) {
            const int t = tid + 256 * k;
            if (t < TO * TO) {
                const int tx = t % TO, r = t / TO;
                const int p  = tx & 1;
                const int m0 = (tx + p) >> 1;
                float acc = 0.f;
#pragma unroll
                for (int u = 0; u < 4; u++)
                    acc += wH[2 * u + p] * sh[r][m0 + u]
                         + hH[2 * u + p] * sl[r][m0 + u];
                X[(long)(i0 + r) * ldx + (j0 + tx)] = acc;
            }
        }
        __syncthreads();
    }
}

// ----------------------------------------------------------------------------
// ONE persistent kernel: fwd levels 2..5, then bwd levels 5..2.
// 512 blocks co-resident (__launch_bounds__(256,4): 4*148 = 592 >= 512).
// ----------------------------------------------------------------------------
__global__ __launch_bounds__(256, 4)
void tail_all(float* bufA, float* bufB, float* flat,
              const float* __restrict__ scal,
              const float* pA, const float* pBp, const float* pBm)
{
    __shared__ float pool[3072];
    __shared__ float hH[8], wH[8], hV[8], wV[8];
    const float alpha = *pA, bp = *pBp, bm = *pBm;
    const int tid = threadIdx.x;
    const int nb = gridDim.x;
    const size_t levoff[6] = {0, 12582912, 15728640, 16515072, 16711680, 16760832};
    unsigned bc = 0;

    // ---- forward levels 2..5 ----
    const float* cur = bufB;    // lev1 LL (1024x1024)
    long ldcur = 1024;
    int s = 1024;
    for (int lev = 2; lev <= 5; lev++) {
        if (tid < 8) { hH[tid] = scal[lev * 8 + tid]; hV[tid] = scal[(lev + 1) * 8 + tid]; }
        __syncthreads();
        if (tid < 8) {
            wH[tid] = hH[7 - tid] * ((tid & 1) ? -1.0f : 1.0f);
            wV[tid] = hV[7 - tid] * ((tid & 1) ? -1.0f : 1.0f);
        }
        __syncthreads();
        const int s2 = s >> 1;
        float* fb = flat + levoff[lev];
        float* ll; long ldll; int thr;
        if (lev == 5) { ll = flat + 16773120; ldll = 64; thr = 1; }
        else          { ll = (lev & 1) ? bufB : bufA; ldll = s2; thr = 0; }
        if (lev == 2)
            fwd_tiles<16>(pool, cur, s, ldcur, fb, ll, ldll, thr, hH, wH, hV, wV, alpha, bp, bm, nb);
        else
            fwd_tiles<8>(pool, cur, s, ldcur, fb, ll, ldll, thr, hH, wH, hV, wV, alpha, bp, bm, nb);
        cur = ll; ldcur = ldll; s = s2;
        bc++; grid_barrier(&g_bar, bc * (unsigned)nb);
    }

    // ---- backward levels 5..2 ----
    const float* aprev = flat + 16773120;
    long lda = 64;
    for (int lev = 5; lev >= 2; lev--) {
        if (tid < 8) { hH[tid] = scal[lev * 8 + tid]; hV[tid] = scal[(lev + 1) * 8 + tid]; }
        __syncthreads();
        if (tid < 8) {
            wH[tid] = hH[7 - tid] * ((tid & 1) ? -1.0f : 1.0f);
            wV[tid] = hV[7 - tid] * ((tid & 1) ? -1.0f : 1.0f);
        }
        __syncthreads();
        const int s2 = 2048 >> lev;
        const float* base = flat + levoff[lev];
        float* xo = (lev & 1) ? bufB : bufA;
        long ldx = 2 * s2;
        if (lev == 2)
            bwd_tiles<32>(pool, base, aprev, lda, s2, xo, ldx, hH, wH, hV, wV, nb);
        else
            bwd_tiles<16>(pool, base, aprev, lda, s2, xo, ldx, hH, wH, hV, wV, nb);
        aprev = xo; lda = ldx;
        if (lev > 2) { bc++; grid_barrier(&g_bar, bc * (unsigned)nb); }
    }
}

// ----------------------------------------------------------------------------
// Host orchestration (graph-capturable: kernel launches only).
// ----------------------------------------------------------------------------
extern "C" void kernel_launch(void* const* d_in, const int* in_sizes, int n_in,
                              void* d_out, int out_size)
{
    const float* x    = (const float*)d_in[0];
    const float* scal = (const float*)d_in[1];
    const float* pA   = (const float*)d_in[2];
    const float* pBp  = (const float*)d_in[3];
    const float* pBm  = (const float*)d_in[4];

    float* out  = (float*)d_out;
    float* flat = out + (size_t)NSIDE * NSIDE;

    float *bufA, *bufB;
    cudaGetSymbolAddress((void**)&bufA, g_bufA);
    cudaGetSymbolAddress((void**)&bufB, g_bufB);

    init_bars<<<1, 1>>>();

    // forward level 0: x (4096) -> flat lev0 + bufA (2048)
    fwd2d32<<<dim3(64, 64), 256>>>(x, 4096, 4096,
                                   flat, bufA, 2048, 0,
                                   scal, scal + 8, pA, pBp, pBm);
    // forward level 1: bufA (2048) -> flat lev1 + bufB (1024)
    fwd2d32<<<dim3(32, 32), 256>>>(bufA, 2048, 2048,
                                   flat + 12582912, bufB, 1024, 0,
                                   scal + 8, scal + 16, pA, pBp, pBm);
    // levels 2..5 fwd + 5..2 bwd (single persistent kernel) -> bufA (1024)
    tail_all<<<NB_TAIL, 256>>>(bufA, bufB, flat, scal, pA, pBp, pBm);

    // backward level 1: coeffs lev1 + bufA (1024) -> bufB (2048)
    bwd2d64<<<dim3(32, 32), 256>>>(flat + 12582912, bufA, 1024,
                                   1024, bufB, 2048,
                                   scal + 8, scal + 16);
    // backward level 0: coeffs lev0 + bufB (2048) -> out (4096)
    bwd2d64<<<dim3(64, 64), 256>>>(flat, bufB, 2048,
                                   2048, out, 4096,
                                   scal, scal + 8);
}